// round 1
// baseline (speedup 1.0000x reference)
#include <cuda_runtime.h>
#include <cstdint>

// Shapes (fixed by the problem)
#define B 8
#define D 256
#define HW (128 * 128)        // 16384
#define C 80
#define NPIX (B * HW)         // 131072
#define RANGE_EXTENDER 10.0f
#define EPS 1e-8f

// Pre-scaled, transposed weights: g_w[d * C + c] = w[c][d]/||w_c|| * asf[c] * 10
__device__ float g_w[D * C];

// ---------------------------------------------------------------------------
// Kernel 1: normalize + scale weights, transpose to [D][C]
// 80 blocks (one per channel) x 256 threads (one per d)
// ---------------------------------------------------------------------------
__global__ void prep_weights_kernel(const float* __restrict__ w,
                                    const float* __restrict__ asf) {
    int c = blockIdx.x;
    int d = threadIdx.x;
    float v = w[c * D + d];

    __shared__ float red[D];
    red[d] = v * v;
    __syncthreads();
    #pragma unroll
    for (int s = D / 2; s > 0; s >>= 1) {
        if (d < s) red[d] += red[d + s];
        __syncthreads();
    }
    float norm = sqrtf(red[0]);
    float scale = asf[c] * RANGE_EXTENDER / fmaxf(norm, EPS);
    g_w[d * C + c] = v * scale;
}

// ---------------------------------------------------------------------------
// Kernel 2: fused normalize-x + GEMM.
// One thread per pixel. 80 fp32 accumulators in registers.
// Weights staged through shared memory in K-chunks of 64 ([64][80] = 20KB).
// x is read exactly once; norm computed in the same pass.
// ---------------------------------------------------------------------------
#define KT 64
__global__ __launch_bounds__(256, 2)
void coshead_main_kernel(const float* __restrict__ x, float* __restrict__ out) {
    __shared__ float ws[KT * C];   // [d_local][c]

    const int tid   = threadIdx.x;
    const int pixel = blockIdx.x * 256 + tid;
    const int b     = pixel >> 14;        // / HW
    const int hw    = pixel & (HW - 1);   // % HW

    const float* xb = x + ((size_t)b * D) * HW + hw;

    float acc[C];
    #pragma unroll
    for (int c = 0; c < C; c++) acc[c] = 0.0f;
    float norm2 = 0.0f;

    for (int kt = 0; kt < D / KT; kt++) {
        __syncthreads();
        // cooperative load: KT*C = 5120 floats, 20 per thread, coalesced
        #pragma unroll
        for (int i = 0; i < (KT * C) / 256; i++) {
            int idx = tid + i * 256;
            ws[idx] = g_w[kt * (KT * C) + idx];
        }
        __syncthreads();

        #pragma unroll 4
        for (int d = 0; d < KT; d++) {
            float xv = xb[(size_t)(kt * KT + d) * HW];
            norm2 = fmaf(xv, xv, norm2);
            const float* wrow = &ws[d * C];
            #pragma unroll
            for (int c = 0; c < C; c += 4) {
                float4 w4 = *reinterpret_cast<const float4*>(wrow + c);
                acc[c + 0] = fmaf(xv, w4.x, acc[c + 0]);
                acc[c + 1] = fmaf(xv, w4.y, acc[c + 1]);
                acc[c + 2] = fmaf(xv, w4.z, acc[c + 2]);
                acc[c + 3] = fmaf(xv, w4.w, acc[c + 3]);
            }
        }
    }

    const float inv = 1.0f / fmaxf(sqrtf(norm2), EPS);
    float* ob = out + ((size_t)b * C) * HW + hw;
    #pragma unroll
    for (int c = 0; c < C; c++) {
        ob[(size_t)c * HW] = acc[c] * inv;
    }
}

// ---------------------------------------------------------------------------
// Launch
// ---------------------------------------------------------------------------
extern "C" void kernel_launch(void* const* d_in, const int* in_sizes, int n_in,
                              void* d_out, int out_size) {
    const float* x   = (const float*)d_in[0];  // [B, D, H, W]
    const float* w   = (const float*)d_in[1];  // [C, D]
    const float* asf = (const float*)d_in[2];  // [C]
    float* out = (float*)d_out;                // [B, C, H, W]

    prep_weights_kernel<<<C, D>>>(w, asf);
    coshead_main_kernel<<<NPIX / 256, 256>>>(x, out);
}